// round 6
// baseline (speedup 1.0000x reference)
#include <cuda_runtime.h>
#include <math.h>

#define N_ 4096
#define HD 32
#define KNUM 2048
#define SCALE 0.17677669529663687f

// scratch (__device__ globals: allocation-free rule)
__device__ float g_qkv[768 * N_];
__device__ float g_q[8 * N_ * HD];
__device__ float g_k[8 * N_ * HD];
__device__ float g_v[8 * N_ * HD];
__device__ float g_attn[256 * N_];
__device__ float g_proj[256 * N_];

// smem layout of k_attn (float offsets)
#define SC_OFF 0
#define KT_OFF 32768
#define QS_OFF 41984
#define HI_OFF 42240
#define RS_OFF 44288
#define SM_TOT 44320

// ---------------- SGEMM: C[M][4096] = A[M][256] * B[256][4096] ----------------
__global__ void __launch_bounds__(256) k_sgemm(const float* __restrict__ A,
                                               const float* __restrict__ Bx, int mode) {
    const float* B = mode ? (const float*)g_attn : Bx;
    float* C = mode ? g_proj : g_qkv;
    __shared__ float As[64][17];
    __shared__ float Bs[16][128];
    int t = threadIdx.x;
    int bm = blockIdx.y * 64, bn = blockIdx.x * 128;
    int tr = t >> 4, tc = t & 15;
    int arow = t >> 2, akk = (t & 3) * 4;
    int brow = t >> 4, bcol = (t & 15) * 8;
    float acc[4][8];
#pragma unroll
    for (int i = 0; i < 4; i++)
#pragma unroll
        for (int j = 0; j < 8; j++) acc[i][j] = 0.f;
    for (int k0 = 0; k0 < 256; k0 += 16) {
        float4 a4 = *(const float4*)&A[(bm + arow) * 256 + k0 + akk];
        float4 b0 = *(const float4*)&B[(size_t)(k0 + brow) * N_ + bn + bcol];
        float4 b1 = *(const float4*)&B[(size_t)(k0 + brow) * N_ + bn + bcol + 4];
        __syncthreads();
        As[arow][akk + 0] = a4.x; As[arow][akk + 1] = a4.y;
        As[arow][akk + 2] = a4.z; As[arow][akk + 3] = a4.w;
        *(float4*)&Bs[brow][bcol] = b0;
        *(float4*)&Bs[brow][bcol + 4] = b1;
        __syncthreads();
#pragma unroll
        for (int k = 0; k < 16; k++) {
            float4 bv0 = *(const float4*)&Bs[k][tc * 4];
            float4 bv1 = *(const float4*)&Bs[k][64 + tc * 4];
#pragma unroll
            for (int i = 0; i < 4; i++) {
                float a = As[tr * 4 + i][k];
                acc[i][0] += a * bv0.x; acc[i][1] += a * bv0.y;
                acc[i][2] += a * bv0.z; acc[i][3] += a * bv0.w;
                acc[i][4] += a * bv1.x; acc[i][5] += a * bv1.y;
                acc[i][6] += a * bv1.z; acc[i][7] += a * bv1.w;
            }
        }
    }
#pragma unroll
    for (int i = 0; i < 4; i++) {
        size_t row = bm + tr * 4 + i;
        *(float4*)&C[row * N_ + bn + tc * 4] =
            make_float4(acc[i][0], acc[i][1], acc[i][2], acc[i][3]);
        *(float4*)&C[row * N_ + bn + 64 + tc * 4] =
            make_float4(acc[i][4], acc[i][5], acc[i][6], acc[i][7]);
    }
}

// ---------- transpose [3C][N] -> [h][n][d] with l2norm for q,k ----------
__global__ void __launch_bounds__(256) k_prep() {
    int which = blockIdx.y;                         // 0=q 1=k 2=v
    int idx = blockIdx.x * 256 + threadIdx.x;       // h*4096+n
    int h = idx >> 12, n = idx & 4095;
    const float* src = g_qkv + (size_t)(which * 256 + h * 32) * N_ + n;
    float s[32], ss = 0.f;
#pragma unroll
    for (int d = 0; d < 32; d++) { s[d] = src[(size_t)d * N_]; ss += s[d] * s[d]; }
    float inv = 1.f;
    if (which < 2) inv = 1.f / fmaxf(sqrtf(ss), 1e-12f);
    float* dst = (which == 0 ? g_q : which == 1 ? g_k : g_v) + (size_t)idx * 32;
#pragma unroll
    for (int d = 0; d < 32; d++) dst[d] = s[d] * inv;
}

// ---------------- fused attention: QK, radix topk, softmax, AV ----------------
__global__ void __launch_bounds__(256) k_attn() {
    extern __shared__ float sm[];
    float* scores = sm + SC_OFF;     // [8][4096]
    float* tile   = sm + KT_OFF;     // [256][36]
    float* qs     = sm + QS_OFF;     // [8][32]
    int*   hist   = (int*)(sm + HI_OFF);   // [8][256]
    float* rowinv = sm + RS_OFF;     // [8]

    int h = blockIdx.y;
    int row0 = blockIdx.x * 8;
    int t = threadIdx.x, w = t >> 5, l = t & 31;
    const float* Q = g_q + (size_t)h * N_ * HD;
    const float* K = g_k + (size_t)h * N_ * HD;
    const float* V = g_v + (size_t)h * N_ * HD;

    if (t < 64) {   // 8 rows * 8 float4
        int r = t >> 3;
        ((float4*)qs)[t] = ((const float4*)(Q + (size_t)(row0 + r) * HD))[t & 7];
    }
    __syncthreads();

    // ---- Phase 1: QK scores (warp covers 8 rows x 32 keys of each 256-key tile)
    for (int tb = 0; tb < N_; tb += 256) {
        const float4* src = (const float4*)(K + (size_t)tb * HD);
#pragma unroll
        for (int i = 0; i < 8; i++)
            *(float4*)&tile[t * 36 + i * 4] = src[t * 8 + i];
        __syncthreads();
        int key = w * 32 + l;
        float acc[8];
#pragma unroll
        for (int r = 0; r < 8; r++) acc[r] = 0.f;
#pragma unroll
        for (int dc = 0; dc < 8; dc++) {
            float4 kv = *(float4*)&tile[key * 36 + dc * 4];
#pragma unroll
            for (int r = 0; r < 8; r++) {
                float4 qv = *(float4*)&qs[r * 32 + dc * 4];
                acc[r] += qv.x * kv.x + qv.y * kv.y + qv.z * kv.z + qv.w * kv.w;
            }
        }
#pragma unroll
        for (int r = 0; r < 8; r++) {
            float s = fminf(fmaxf(acc[r] * SCALE, -32.f), 32.f);
            scores[r * N_ + tb + key] = s;
        }
        __syncthreads();
    }

    // ---- Phase 2: exact k-th largest per row via 4-pass radix select (warp w -> row w)
    float* srow = scores + w * N_;
    unsigned prefix = 0; int want = KNUM;
    for (int j = 3; j >= 0; j--) {
        for (int b = l; b < 256; b += 32) hist[w * 256 + b] = 0;
        __syncwarp();
        for (int i = l; i < N_; i += 32) {
            unsigned bb = __float_as_uint(srow[i]);
            unsigned u = (bb & 0x80000000u) ? ~bb : (bb | 0x80000000u);
            bool ok = true;
            if (j < 3) ok = ((u >> ((j + 1) * 8)) == prefix);
            if (ok) atomicAdd(&hist[w * 256 + ((u >> (j * 8)) & 255u)], 1);
        }
        __syncwarp();
        unsigned sel = 0; int nw = want;
        if (l == 0) {
            int cum = 0;
            for (int b = 255; b >= 0; b--) {
                int c = hist[w * 256 + b];
                if (cum + c >= want) { sel = (unsigned)b; nw = want - cum; break; }
                cum += c;
            }
        }
        sel = __shfl_sync(0xffffffffu, sel, 0);
        nw  = __shfl_sync(0xffffffffu, nw, 0);
        prefix = (prefix << 8) | sel;
        want = nw;
        __syncwarp();
    }
    unsigned T = prefix;   // uint key of exact k-th largest

    // ---- Phase 3: row max, masked exp, sum
    float m = -1e30f;
    for (int i = l; i < N_; i += 32) m = fmaxf(m, srow[i]);
#pragma unroll
    for (int o = 16; o; o >>= 1) m = fmaxf(m, __shfl_xor_sync(0xffffffffu, m, o));
    float sum = 0.f;
    for (int i = l; i < N_; i += 32) {
        float s = srow[i];
        unsigned bb = __float_as_uint(s);
        unsigned u = (bb & 0x80000000u) ? ~bb : (bb | 0x80000000u);
        float p = (u >= T) ? __expf(s - m) : 0.f;
        srow[i] = p;
        sum += p;
    }
#pragma unroll
    for (int o = 16; o; o >>= 1) sum += __shfl_xor_sync(0xffffffffu, sum, o);
    if (l == 0) rowinv[w] = 1.f / sum;
    __syncthreads();

    // ---- Phase 4: AV (lane=dim, 8 row accumulators; warps split n)
    float acc[8];
#pragma unroll
    for (int r = 0; r < 8; r++) acc[r] = 0.f;
    for (int tb = 0; tb < N_; tb += 256) {
        const float4* src = (const float4*)(V + (size_t)tb * HD);
#pragma unroll
        for (int i = 0; i < 8; i++)
            *(float4*)&tile[t * 36 + i * 4] = src[t * 8 + i];
        __syncthreads();
#pragma unroll
        for (int g = 0; g < 8; g++) {
            int n0 = w * 32 + g * 4;
            float4 p[8];
#pragma unroll
            for (int r = 0; r < 8; r++) p[r] = *(float4*)&scores[r * N_ + tb + n0];
            float v0 = tile[(n0 + 0) * 36 + l];
            float v1 = tile[(n0 + 1) * 36 + l];
            float v2 = tile[(n0 + 2) * 36 + l];
            float v3 = tile[(n0 + 3) * 36 + l];
#pragma unroll
            for (int r = 0; r < 8; r++)
                acc[r] += p[r].x * v0 + p[r].y * v1 + p[r].z * v2 + p[r].w * v3;
        }
        __syncthreads();
    }
    // cross-warp reduce partials (reuse tile buffer)
    float* red = tile;
#pragma unroll
    for (int r = 0; r < 8; r++) red[w * 256 + r * 32 + l] = acc[r];
    __syncthreads();
    {
        int r = w, d = l;
        float o = 0.f;
#pragma unroll
        for (int ww = 0; ww < 8; ww++) o += red[ww * 256 + r * 32 + d];
        o *= rowinv[r];
        g_attn[(size_t)(h * 32 + d) * N_ + row0 + r] = o;
    }
}

// ---------------- GroupNorm(32 groups) ----------------
__global__ void __launch_bounds__(256) k_gn(const float* __restrict__ gamma,
                                            const float* __restrict__ beta,
                                            float* __restrict__ out) {
    __shared__ float rs[2][8];
    int g = blockIdx.x, t = threadIdx.x;
    const float* src = g_proj + (size_t)g * 8 * N_;
    float sum = 0.f, sq = 0.f;
    for (int i = t; i < 8 * N_; i += 256) { float v = src[i]; sum += v; sq += v * v; }
#pragma unroll
    for (int o = 16; o; o >>= 1) {
        sum += __shfl_xor_sync(0xffffffffu, sum, o);
        sq  += __shfl_xor_sync(0xffffffffu, sq, o);
    }
    if ((t & 31) == 0) { rs[0][t >> 5] = sum; rs[1][t >> 5] = sq; }
    __syncthreads();
    if (t < 32) {
        float a = (t < 8) ? rs[0][t] : 0.f;
        float b = (t < 8) ? rs[1][t] : 0.f;
#pragma unroll
        for (int o = 4; o; o >>= 1) {
            a += __shfl_xor_sync(0xffffffffu, a, o);
            b += __shfl_xor_sync(0xffffffffu, b, o);
        }
        if (t == 0) { rs[0][0] = a; rs[1][0] = b; }
    }
    __syncthreads();
    float inv_m = 1.f / (8.f * N_);
    float mean = rs[0][0] * inv_m;
    float var = rs[1][0] * inv_m - mean * mean;
    float rstd = rsqrtf(var + 1e-6f);
    for (int i = t; i < 8 * N_; i += 256) {
        int c = g * 8 + (i >> 12);
        out[(size_t)g * 8 * N_ + i] = (src[i] - mean) * rstd * gamma[c] + beta[c];
    }
}

extern "C" void kernel_launch(void* const* d_in, const int* in_sizes, int n_in,
                              void* d_out, int out_size) {
    (void)in_sizes; (void)n_in; (void)out_size;
    const float* x      = (const float*)d_in[0];
    const float* w_qkv  = (const float*)d_in[1];
    const float* w_proj = (const float*)d_in[2];
    const float* gamma  = (const float*)d_in[3];
    const float* beta   = (const float*)d_in[4];
    float* out = (float*)d_out;

    cudaFuncSetAttribute(k_attn, cudaFuncAttributeMaxDynamicSharedMemorySize,
                         SM_TOT * (int)sizeof(float));

    k_sgemm<<<dim3(32, 12), 256>>>(w_qkv, x, 0);          // qkv: [768][4096]
    k_prep<<<dim3(128, 3), 256>>>();                       // q,k l2norm + transpose; v transpose
    k_attn<<<dim3(512, 8), 256, SM_TOT * sizeof(float)>>>();
    k_sgemm<<<dim3(32, 4), 256>>>(w_proj, nullptr, 1);     // proj: [256][4096]
    k_gn<<<32, 256>>>(gamma, beta, out);
}

// round 7
// speedup vs baseline: 1.0289x; 1.0289x over previous
#include <cuda_runtime.h>
#include <math.h>

#define N_ 4096
#define HD 32
#define KNUM 2048
#define SCALE 0.17677669529663687f

// scratch (__device__ globals: allocation-free rule)
__device__ float g_qkv[768 * N_];
__device__ float g_q[8 * N_ * HD];
__device__ float g_k[8 * N_ * HD];
__device__ float g_v[8 * N_ * HD];
__device__ float g_attn[256 * N_];
__device__ float g_proj[256 * N_];

// smem layout of k_attn (float offsets)
#define SC_OFF 0            // scores [8][4096]
#define KT_OFF 32768        // tile   [512][36]
#define QS_OFF 51200        // qs     [8][32]
#define HI_OFF 51456        // hist   [8][256] (int)
#define PX_OFF 53504        // s_prefix [8] (uint)
#define WT_OFF 53512        // s_want   [8] (int)
#define PS_OFF 53520        // s_psum   [8][2]
#define RI_OFF 53536        // rowinv   [8]
#define SM_TOT 53544

// ---------------- SGEMM: C[M][4096] = A[M][256] * B[256][4096] ----------------
__global__ void __launch_bounds__(256) k_sgemm(const float* __restrict__ A,
                                               const float* __restrict__ Bx, int mode) {
    const float* B = mode ? (const float*)g_attn : Bx;
    float* C = mode ? g_proj : g_qkv;
    __shared__ float As[64][17];
    __shared__ float Bs[16][128];
    int t = threadIdx.x;
    int bm = blockIdx.y * 64, bn = blockIdx.x * 128;
    int tr = t >> 4, tc = t & 15;
    int arow = t >> 2, akk = (t & 3) * 4;
    int brow = t >> 4, bcol = (t & 15) * 8;
    float acc[4][8];
#pragma unroll
    for (int i = 0; i < 4; i++)
#pragma unroll
        for (int j = 0; j < 8; j++) acc[i][j] = 0.f;
    for (int k0 = 0; k0 < 256; k0 += 16) {
        float4 a4 = *(const float4*)&A[(bm + arow) * 256 + k0 + akk];
        float4 b0 = *(const float4*)&B[(size_t)(k0 + brow) * N_ + bn + bcol];
        float4 b1 = *(const float4*)&B[(size_t)(k0 + brow) * N_ + bn + bcol + 4];
        __syncthreads();
        As[arow][akk + 0] = a4.x; As[arow][akk + 1] = a4.y;
        As[arow][akk + 2] = a4.z; As[arow][akk + 3] = a4.w;
        *(float4*)&Bs[brow][bcol] = b0;
        *(float4*)&Bs[brow][bcol + 4] = b1;
        __syncthreads();
#pragma unroll
        for (int k = 0; k < 16; k++) {
            float4 bv0 = *(const float4*)&Bs[k][tc * 4];
            float4 bv1 = *(const float4*)&Bs[k][64 + tc * 4];
#pragma unroll
            for (int i = 0; i < 4; i++) {
                float a = As[tr * 4 + i][k];
                acc[i][0] += a * bv0.x; acc[i][1] += a * bv0.y;
                acc[i][2] += a * bv0.z; acc[i][3] += a * bv0.w;
                acc[i][4] += a * bv1.x; acc[i][5] += a * bv1.y;
                acc[i][6] += a * bv1.z; acc[i][7] += a * bv1.w;
            }
        }
    }
#pragma unroll
    for (int i = 0; i < 4; i++) {
        size_t row = bm + tr * 4 + i;
        *(float4*)&C[row * N_ + bn + tc * 4] =
            make_float4(acc[i][0], acc[i][1], acc[i][2], acc[i][3]);
        *(float4*)&C[row * N_ + bn + 64 + tc * 4] =
            make_float4(acc[i][4], acc[i][5], acc[i][6], acc[i][7]);
    }
}

// ---------- transpose [3C][N] -> [h][n][d] with l2norm for q,k ----------
__global__ void __launch_bounds__(256) k_prep() {
    int which = blockIdx.y;                         // 0=q 1=k 2=v
    int idx = blockIdx.x * 256 + threadIdx.x;       // h*4096+n
    int h = idx >> 12, n = idx & 4095;
    const float* src = g_qkv + (size_t)(which * 256 + h * 32) * N_ + n;
    float s[32], ss = 0.f;
#pragma unroll
    for (int d = 0; d < 32; d++) { s[d] = src[(size_t)d * N_]; ss += s[d] * s[d]; }
    float inv = 1.f;
    if (which < 2) inv = 1.f / fmaxf(sqrtf(ss), 1e-12f);
    float* dst = (which == 0 ? g_q : which == 1 ? g_k : g_v) + (size_t)idx * 32;
#pragma unroll
    for (int d = 0; d < 32; d++) dst[d] = s[d] * inv;
}

// ---------------- fused attention: QK, radix topk, softmax, AV ----------------
// 512 threads (16 warps), 512-key tiles, register prefetch of next tile.
__global__ void __launch_bounds__(512) k_attn() {
    extern __shared__ float sm[];
    float*    scores  = sm + SC_OFF;            // [8][4096]
    float*    tile    = sm + KT_OFF;            // [512][36]
    float*    qs      = sm + QS_OFF;            // [8][32]
    int*      hist    = (int*)(sm + HI_OFF);    // [8][256]
    unsigned* sprefix = (unsigned*)(sm + PX_OFF);
    int*      swant   = (int*)(sm + WT_OFF);
    float*    psum    = sm + PS_OFF;            // [8][2]
    float*    rowinv  = sm + RI_OFF;            // [8]

    int h = blockIdx.y;
    int row0 = blockIdx.x * 8;
    int t = threadIdx.x, w = t >> 5, l = t & 31;
    const float* Q = g_q + (size_t)h * N_ * HD;
    const float* K = g_k + (size_t)h * N_ * HD;
    const float* V = g_v + (size_t)h * N_ * HD;

    if (t < 64) {   // 8 rows * 8 float4
        int r = t >> 3;
        ((float4*)qs)[t] = ((const float4*)(Q + (size_t)(row0 + r) * HD))[t & 7];
    }
    if (t < 8) { sprefix[t] = 0u; swant[t] = KNUM; }

    // ---- Phase 1: QK scores. Tile = 512 keys; warp w -> keys [w*32, w*32+32).
    {
        const float4* src = (const float4*)K;   // 8 float4 per key
        float4 pf[8];
#pragma unroll
        for (int i = 0; i < 8; i++) pf[i] = src[t * 8 + i];
        for (int tb = 0; tb < N_; tb += 512) {
            __syncthreads();
#pragma unroll
            for (int i = 0; i < 8; i++) *(float4*)&tile[t * 36 + i * 4] = pf[i];
            __syncthreads();
            if (tb + 512 < N_) {
                const float4* nsrc = (const float4*)(K + (size_t)(tb + 512) * HD);
#pragma unroll
                for (int i = 0; i < 8; i++) pf[i] = nsrc[t * 8 + i];
            }
            int key = w * 32 + l;
            float acc[8];
#pragma unroll
            for (int r = 0; r < 8; r++) acc[r] = 0.f;
#pragma unroll
            for (int dc = 0; dc < 8; dc++) {
                float4 kv = *(float4*)&tile[key * 36 + dc * 4];
#pragma unroll
                for (int r = 0; r < 8; r++) {
                    float4 qv = *(float4*)&qs[r * 32 + dc * 4];
                    acc[r] += qv.x * kv.x + qv.y * kv.y + qv.z * kv.z + qv.w * kv.w;
                }
            }
#pragma unroll
            for (int r = 0; r < 8; r++) {
                float s = fminf(fmaxf(acc[r] * SCALE, -32.f), 32.f);
                scores[r * N_ + tb + key] = s;
            }
        }
    }

    // ---- Phase 2: exact k-th largest per row, 4-pass radix select.
    // Rows 0..7; row r scanned by warps 2r and 2r+1 (sub-lane 0..63).
    int r = w >> 1;
    int sub = (w & 1) * 32 + l;
    float* srow = scores + r * N_;
    for (int j = 3; j >= 0; j--) {
        for (int b = t; b < 2048; b += 512) ((int*)hist)[b] = 0;
        __syncthreads();
        unsigned prefix = sprefix[r];
        for (int i = sub; i < N_; i += 64) {
            unsigned bb = __float_as_uint(srow[i]);
            unsigned u = (bb & 0x80000000u) ? ~bb : (bb | 0x80000000u);
            bool ok = (j == 3) || ((u >> ((j + 1) * 8)) == prefix);
            if (ok) atomicAdd(&hist[r * 256 + ((u >> (j * 8)) & 255u)], 1);
        }
        __syncthreads();
        if ((t & 63) == 0) {          // one selector thread per row (w = 2r, l = 0)
            int want = swant[r];
            int cum = 0; unsigned sel = 0;
            for (int b = 255; b >= 0; b--) {
                int c = hist[r * 256 + b];
                if (cum + c >= want) { sel = (unsigned)b; swant[r] = want - cum; break; }
                cum += c;
            }
            sprefix[r] = (sprefix[r] << 8) | sel;
        }
        __syncthreads();
    }
    unsigned T = sprefix[r];          // uint key of exact k-th largest

    // ---- Phase 3: masked exp + sum (no max shift needed: |s| <= 0.177)
    {
        float sum = 0.f;
        for (int i = sub; i < N_; i += 64) {
            float s = srow[i];
            unsigned bb = __float_as_uint(s);
            unsigned u = (bb & 0x80000000u) ? ~bb : (bb | 0x80000000u);
            float p = (u >= T) ? __expf(s) : 0.f;
            srow[i] = p;
            sum += p;
        }
#pragma unroll
        for (int o = 16; o; o >>= 1) sum += __shfl_xor_sync(0xffffffffu, sum, o);
        if (l == 0) psum[r * 2 + (w & 1)] = sum;
        __syncthreads();
        if (t < 8) rowinv[t] = 1.f / (psum[t * 2] + psum[t * 2 + 1]);
    }

    // ---- Phase 4: AV. Same tiling; warp w -> keys [w*32, w*32+32) per tile.
    float acc[8];
#pragma unroll
    for (int rr = 0; rr < 8; rr++) acc[rr] = 0.f;
    {
        const float4* src = (const float4*)V;
        float4 pf[8];
#pragma unroll
        for (int i = 0; i < 8; i++) pf[i] = src[t * 8 + i];
        for (int tb = 0; tb < N_; tb += 512) {
            __syncthreads();
#pragma unroll
            for (int i = 0; i < 8; i++) *(float4*)&tile[t * 36 + i * 4] = pf[i];
            __syncthreads();
            if (tb + 512 < N_) {
                const float4* nsrc = (const float4*)(V + (size_t)(tb + 512) * HD);
#pragma unroll
                for (int i = 0; i < 8; i++) pf[i] = nsrc[t * 8 + i];
            }
#pragma unroll
            for (int g = 0; g < 8; g++) {
                int n0 = w * 32 + g * 4;
                float4 p[8];
#pragma unroll
                for (int rr = 0; rr < 8; rr++)
                    p[rr] = *(float4*)&scores[rr * N_ + tb + n0];
                float v0 = tile[(n0 + 0) * 36 + l];
                float v1 = tile[(n0 + 1) * 36 + l];
                float v2 = tile[(n0 + 2) * 36 + l];
                float v3 = tile[(n0 + 3) * 36 + l];
#pragma unroll
                for (int rr = 0; rr < 8; rr++)
                    acc[rr] += p[rr].x * v0 + p[rr].y * v1 + p[rr].z * v2 + p[rr].w * v3;
            }
        }
    }
    // cross-warp reduce partials (reuse tile buffer: 16 warps x 8 rows x 32 dims)
    __syncthreads();
    float* red = tile;
#pragma unroll
    for (int rr = 0; rr < 8; rr++) red[w * 256 + rr * 32 + l] = acc[rr];
    __syncthreads();
    if (t < 256) {
        int rr = t >> 5, d = t & 31;
        float o = 0.f;
#pragma unroll
        for (int ww = 0; ww < 16; ww++) o += red[ww * 256 + rr * 32 + d];
        o *= rowinv[rr];
        g_attn[(size_t)(h * 32 + d) * N_ + row0 + rr] = o;
    }
}

// ---------------- GroupNorm(32 groups) ----------------
__global__ void __launch_bounds__(256) k_gn(const float* __restrict__ gamma,
                                            const float* __restrict__ beta,
                                            float* __restrict__ out) {
    __shared__ float rs[2][8];
    int g = blockIdx.x, t = threadIdx.x;
    const float* src = g_proj + (size_t)g * 8 * N_;
    float sum = 0.f, sq = 0.f;
    for (int i = t; i < 8 * N_; i += 256) { float v = src[i]; sum += v; sq += v * v; }
#pragma unroll
    for (int o = 16; o; o >>= 1) {
        sum += __shfl_xor_sync(0xffffffffu, sum, o);
        sq  += __shfl_xor_sync(0xffffffffu, sq, o);
    }
    if ((t & 31) == 0) { rs[0][t >> 5] = sum; rs[1][t >> 5] = sq; }
    __syncthreads();
    if (t < 32) {
        float a = (t < 8) ? rs[0][t] : 0.f;
        float b = (t < 8) ? rs[1][t] : 0.f;
#pragma unroll
        for (int o = 4; o; o >>= 1) {
            a += __shfl_xor_sync(0xffffffffu, a, o);
            b += __shfl_xor_sync(0xffffffffu, b, o);
        }
        if (t == 0) { rs[0][0] = a; rs[1][0] = b; }
    }
    __syncthreads();
    float inv_m = 1.f / (8.f * N_);
    float mean = rs[0][0] * inv_m;
    float var = rs[1][0] * inv_m - mean * mean;
    float rstd = rsqrtf(var + 1e-6f);
    for (int i = t; i < 8 * N_; i += 256) {
        int c = g * 8 + (i >> 12);
        out[(size_t)g * 8 * N_ + i] = (src[i] - mean) * rstd * gamma[c] + beta[c];
    }
}

extern "C" void kernel_launch(void* const* d_in, const int* in_sizes, int n_in,
                              void* d_out, int out_size) {
    (void)in_sizes; (void)n_in; (void)out_size;
    const float* x      = (const float*)d_in[0];
    const float* w_qkv  = (const float*)d_in[1];
    const float* w_proj = (const float*)d_in[2];
    const float* gamma  = (const float*)d_in[3];
    const float* beta   = (const float*)d_in[4];
    float* out = (float*)d_out;

    cudaFuncSetAttribute(k_attn, cudaFuncAttributeMaxDynamicSharedMemorySize,
                         SM_TOT * (int)sizeof(float));

    k_sgemm<<<dim3(32, 12), 256>>>(w_qkv, x, 0);          // qkv: [768][4096]
    k_prep<<<dim3(128, 3), 256>>>();                       // q,k l2norm + transpose; v transpose
    k_attn<<<dim3(512, 8), 512, SM_TOT * sizeof(float)>>>();
    k_sgemm<<<dim3(32, 4), 256>>>(w_proj, nullptr, 1);     // proj: [256][4096]
    k_gn<<<32, 256>>>(gamma, beta, out);
}

// round 8
// speedup vs baseline: 1.0492x; 1.0198x over previous
#include <cuda_runtime.h>
#include <math.h>

#define N_ 4096
#define HD 32
#define KNUM 2048
#define SCALE 0.17677669529663687f

// scratch (__device__ globals: allocation-free rule)
__device__ float g_qkv[768 * N_];
__device__ float g_q[8 * N_ * HD];
__device__ float g_k[8 * N_ * HD];
__device__ float g_v[8 * N_ * HD];
__device__ float g_attn[256 * N_];
__device__ float g_proj[256 * N_];

// smem layout of k_attn (float offsets)
#define SC_OFF 0            // scores [8][4096]
#define KT_OFF 32768        // tile   [512][36]
#define QS_OFF 51200        // qs     [8][32]
#define HI_OFF 51456        // hist   [8][256] (int)
#define PX_OFF 53504        // s_prefix [8] (uint)
#define WT_OFF 53512        // s_want   [8] (int)
#define PS_OFF 53520        // s_psum   [8][2]
#define RI_OFF 53536        // rowinv   [8]
#define SM_TOT 53544

// ---------------- SGEMM: C[M][4096] = A[M][256] * B[256][4096] ----------------
__global__ void __launch_bounds__(256) k_sgemm(const float* __restrict__ A,
                                               const float* __restrict__ Bx, int mode) {
    const float* B = mode ? (const float*)g_attn : Bx;
    float* C = mode ? g_proj : g_qkv;
    __shared__ float As[64][17];
    __shared__ float Bs[16][128];
    int t = threadIdx.x;
    int bm = blockIdx.y * 64, bn = blockIdx.x * 128;
    int tr = t >> 4, tc = t & 15;
    int arow = t >> 2, akk = (t & 3) * 4;
    int brow = t >> 4, bcol = (t & 15) * 8;
    float acc[4][8];
#pragma unroll
    for (int i = 0; i < 4; i++)
#pragma unroll
        for (int j = 0; j < 8; j++) acc[i][j] = 0.f;
    for (int k0 = 0; k0 < 256; k0 += 16) {
        float4 a4 = *(const float4*)&A[(bm + arow) * 256 + k0 + akk];
        float4 b0 = *(const float4*)&B[(size_t)(k0 + brow) * N_ + bn + bcol];
        float4 b1 = *(const float4*)&B[(size_t)(k0 + brow) * N_ + bn + bcol + 4];
        __syncthreads();
        As[arow][akk + 0] = a4.x; As[arow][akk + 1] = a4.y;
        As[arow][akk + 2] = a4.z; As[arow][akk + 3] = a4.w;
        *(float4*)&Bs[brow][bcol] = b0;
        *(float4*)&Bs[brow][bcol + 4] = b1;
        __syncthreads();
#pragma unroll
        for (int k = 0; k < 16; k++) {
            float4 bv0 = *(const float4*)&Bs[k][tc * 4];
            float4 bv1 = *(const float4*)&Bs[k][64 + tc * 4];
#pragma unroll
            for (int i = 0; i < 4; i++) {
                float a = As[tr * 4 + i][k];
                acc[i][0] += a * bv0.x; acc[i][1] += a * bv0.y;
                acc[i][2] += a * bv0.z; acc[i][3] += a * bv0.w;
                acc[i][4] += a * bv1.x; acc[i][5] += a * bv1.y;
                acc[i][6] += a * bv1.z; acc[i][7] += a * bv1.w;
            }
        }
    }
#pragma unroll
    for (int i = 0; i < 4; i++) {
        size_t row = bm + tr * 4 + i;
        *(float4*)&C[row * N_ + bn + tc * 4] =
            make_float4(acc[i][0], acc[i][1], acc[i][2], acc[i][3]);
        *(float4*)&C[row * N_ + bn + 64 + tc * 4] =
            make_float4(acc[i][4], acc[i][5], acc[i][6], acc[i][7]);
    }
}

// ---------- transpose [3C][N] -> [h][n][d] with l2norm for q,k ----------
__global__ void __launch_bounds__(256) k_prep() {
    int which = blockIdx.y;                         // 0=q 1=k 2=v
    int idx = blockIdx.x * 256 + threadIdx.x;       // h*4096+n
    int h = idx >> 12, n = idx & 4095;
    const float* src = g_qkv + (size_t)(which * 256 + h * 32) * N_ + n;
    float s[32], ss = 0.f;
#pragma unroll
    for (int d = 0; d < 32; d++) { s[d] = src[(size_t)d * N_]; ss += s[d] * s[d]; }
    float inv = 1.f;
    if (which < 2) inv = 1.f / fmaxf(sqrtf(ss), 1e-12f);
    float* dst = (which == 0 ? g_q : which == 1 ? g_k : g_v) + (size_t)idx * 32;
#pragma unroll
    for (int d = 0; d < 32; d++) dst[d] = s[d] * inv;
}

// ---------------- fused attention: QK, radix topk, softmax, AV ----------------
// 512 threads (16 warps), 512-key tiles, register prefetch of next tile.
__global__ void __launch_bounds__(512) k_attn() {
    extern __shared__ float sm[];
    float*    scores  = sm + SC_OFF;            // [8][4096]
    float*    tile    = sm + KT_OFF;            // [512][36]
    float*    qs      = sm + QS_OFF;            // [8][32]
    int*      hist    = (int*)(sm + HI_OFF);    // [8][256]
    unsigned* sprefix = (unsigned*)(sm + PX_OFF);
    int*      swant   = (int*)(sm + WT_OFF);
    float*    psum    = sm + PS_OFF;            // [8][2]
    float*    rowinv  = sm + RI_OFF;            // [8]

    int h = blockIdx.y;
    int row0 = blockIdx.x * 8;
    int t = threadIdx.x, w = t >> 5, l = t & 31;
    const float* Q = g_q + (size_t)h * N_ * HD;
    const float* K = g_k + (size_t)h * N_ * HD;
    const float* V = g_v + (size_t)h * N_ * HD;

    if (t < 64) {   // 8 rows * 8 float4
        int r = t >> 3;
        ((float4*)qs)[t] = ((const float4*)(Q + (size_t)(row0 + r) * HD))[t & 7];
    }
    if (t < 8) { sprefix[t] = 0u; swant[t] = KNUM; }

    // ---- Phase 1: QK scores. Tile = 512 keys; warp w -> keys [w*32, w*32+32).
    {
        const float4* src = (const float4*)K;   // 8 float4 per key
        float4 pf[8];
#pragma unroll
        for (int i = 0; i < 8; i++) pf[i] = src[t * 8 + i];
        for (int tb = 0; tb < N_; tb += 512) {
            __syncthreads();
#pragma unroll
            for (int i = 0; i < 8; i++) *(float4*)&tile[t * 36 + i * 4] = pf[i];
            __syncthreads();
            if (tb + 512 < N_) {
                const float4* nsrc = (const float4*)(K + (size_t)(tb + 512) * HD);
#pragma unroll
                for (int i = 0; i < 8; i++) pf[i] = nsrc[t * 8 + i];
            }
            int key = w * 32 + l;
            float acc[8];
#pragma unroll
            for (int r = 0; r < 8; r++) acc[r] = 0.f;
#pragma unroll
            for (int dc = 0; dc < 8; dc++) {
                float4 kv = *(float4*)&tile[key * 36 + dc * 4];
#pragma unroll
                for (int r = 0; r < 8; r++) {
                    float4 qv = *(float4*)&qs[r * 32 + dc * 4];
                    acc[r] += qv.x * kv.x + qv.y * kv.y + qv.z * kv.z + qv.w * kv.w;
                }
            }
#pragma unroll
            for (int r = 0; r < 8; r++) {
                float s = fminf(fmaxf(acc[r] * SCALE, -32.f), 32.f);
                scores[r * N_ + tb + key] = s;
            }
        }
    }

    // ---- Phase 2: exact k-th largest per row, 4-pass radix select.
    // Rows 0..7; row r scanned by warps 2r and 2r+1 (sub-lane 0..63).
    // Histogram adds are warp-aggregated (match_any) to kill same-bank ATOMS
    // serialization; bin selection is a warp-parallel suffix scan.
    int r = w >> 1;
    int sub = (w & 1) * 32 + l;
    float* srow = scores + r * N_;
    for (int j = 3; j >= 0; j--) {
        for (int b = t; b < 2048; b += 512) ((int*)hist)[b] = 0;
        __syncthreads();
        unsigned prefix = sprefix[r];
        for (int i = sub; i < N_; i += 64) {
            unsigned bb = __float_as_uint(srow[i]);
            unsigned u = (bb & 0x80000000u) ? ~bb : (bb | 0x80000000u);
            bool ok = (j == 3) || ((u >> ((j + 1) * 8)) == prefix);
            unsigned bin = ok ? ((u >> (j * 8)) & 255u) : 0xFFFFFFFFu;
            unsigned peers = __match_any_sync(0xffffffffu, bin);
            if (ok && (__ffs(peers) - 1 == l))
                atomicAdd(&hist[r * 256 + bin], __popc(peers));
        }
        __syncthreads();
        if ((w & 1) == 0) {           // warp 2r selects for row r, warp-parallel
            int want = swant[r];
            int base = 255 - l * 8;   // lane l owns 8 descending bins
            int cnt[8]; int local = 0;
#pragma unroll
            for (int i = 0; i < 8; i++) { cnt[i] = hist[r * 256 + base - i]; local += cnt[i]; }
            int pre = local;
#pragma unroll
            for (int o = 1; o < 32; o <<= 1) {
                int x = __shfl_up_sync(0xffffffffu, pre, o);
                if (l >= o) pre += x;
            }
            int cum_before = pre - local;   // counts in bins above this lane's chunk
            if (cum_before < want && cum_before + local >= want) {
                int rem = want - cum_before;
                int c = 0;
#pragma unroll
                for (int i = 0; i < 8; i++) {
                    if (c + cnt[i] >= rem) {
                        sprefix[r] = (sprefix[r] << 8) | (unsigned)(base - i);
                        swant[r] = rem - c;
                        break;
                    }
                    c += cnt[i];
                }
            }
        }
        __syncthreads();
    }
    unsigned T = sprefix[r];          // uint key of exact k-th largest

    // ---- Phase 3: masked exp + sum (no max shift needed: |s| <= 0.177)
    {
        float sum = 0.f;
        for (int i = sub; i < N_; i += 64) {
            float s = srow[i];
            unsigned bb = __float_as_uint(s);
            unsigned u = (bb & 0x80000000u) ? ~bb : (bb | 0x80000000u);
            float p = (u >= T) ? __expf(s) : 0.f;
            srow[i] = p;
            sum += p;
        }
#pragma unroll
        for (int o = 16; o; o >>= 1) sum += __shfl_xor_sync(0xffffffffu, sum, o);
        if (l == 0) psum[r * 2 + (w & 1)] = sum;
        __syncthreads();
        if (t < 8) rowinv[t] = 1.f / (psum[t * 2] + psum[t * 2 + 1]);
    }

    // ---- Phase 4: AV. Same tiling; warp w -> keys [w*32, w*32+32) per tile.
    float acc[8];
#pragma unroll
    for (int rr = 0; rr < 8; rr++) acc[rr] = 0.f;
    {
        const float4* src = (const float4*)V;
        float4 pf[8];
#pragma unroll
        for (int i = 0; i < 8; i++) pf[i] = src[t * 8 + i];
        for (int tb = 0; tb < N_; tb += 512) {
            __syncthreads();
#pragma unroll
            for (int i = 0; i < 8; i++) *(float4*)&tile[t * 36 + i * 4] = pf[i];
            __syncthreads();
            if (tb + 512 < N_) {
                const float4* nsrc = (const float4*)(V + (size_t)(tb + 512) * HD);
#pragma unroll
                for (int i = 0; i < 8; i++) pf[i] = nsrc[t * 8 + i];
            }
#pragma unroll
            for (int g = 0; g < 8; g++) {
                int n0 = w * 32 + g * 4;
                float4 p[8];
#pragma unroll
                for (int rr = 0; rr < 8; rr++)
                    p[rr] = *(float4*)&scores[rr * N_ + tb + n0];
                float v0 = tile[(n0 + 0) * 36 + l];
                float v1 = tile[(n0 + 1) * 36 + l];
                float v2 = tile[(n0 + 2) * 36 + l];
                float v3 = tile[(n0 + 3) * 36 + l];
#pragma unroll
                for (int rr = 0; rr < 8; rr++)
                    acc[rr] += p[rr].x * v0 + p[rr].y * v1 + p[rr].z * v2 + p[rr].w * v3;
            }
        }
    }
    // cross-warp reduce partials (reuse tile buffer: 16 warps x 8 rows x 32 dims)
    __syncthreads();
    float* red = tile;
#pragma unroll
    for (int rr = 0; rr < 8; rr++) red[w * 256 + rr * 32 + l] = acc[rr];
    __syncthreads();
    if (t < 256) {
        int rr = t >> 5, d = t & 31;
        float o = 0.f;
#pragma unroll
        for (int ww = 0; ww < 16; ww++) o += red[ww * 256 + rr * 32 + d];
        o *= rowinv[rr];
        g_attn[(size_t)(h * 32 + d) * N_ + row0 + rr] = o;
    }
}

// ---------------- GroupNorm(32 groups) ----------------
__global__ void __launch_bounds__(256) k_gn(const float* __restrict__ gamma,
                                            const float* __restrict__ beta,
                                            float* __restrict__ out) {
    __shared__ float rs[2][8];
    int g = blockIdx.x, t = threadIdx.x;
    const float* src = g_proj + (size_t)g * 8 * N_;
    float sum = 0.f, sq = 0.f;
    for (int i = t; i < 8 * N_; i += 256) { float v = src[i]; sum += v; sq += v * v; }
#pragma unroll
    for (int o = 16; o; o >>= 1) {
        sum += __shfl_xor_sync(0xffffffffu, sum, o);
        sq  += __shfl_xor_sync(0xffffffffu, sq, o);
    }
    if ((t & 31) == 0) { rs[0][t >> 5] = sum; rs[1][t >> 5] = sq; }
    __syncthreads();
    if (t < 32) {
        float a = (t < 8) ? rs[0][t] : 0.f;
        float b = (t < 8) ? rs[1][t] : 0.f;
#pragma unroll
        for (int o = 4; o; o >>= 1) {
            a += __shfl_xor_sync(0xffffffffu, a, o);
            b += __shfl_xor_sync(0xffffffffu, b, o);
        }
        if (t == 0) { rs[0][0] = a; rs[1][0] = b; }
    }
    __syncthreads();
    float inv_m = 1.f / (8.f * N_);
    float mean = rs[0][0] * inv_m;
    float var = rs[1][0] * inv_m - mean * mean;
    float rstd = rsqrtf(var + 1e-6f);
    for (int i = t; i < 8 * N_; i += 256) {
        int c = g * 8 + (i >> 12);
        out[(size_t)g * 8 * N_ + i] = (src[i] - mean) * rstd * gamma[c] + beta[c];
    }
}

extern "C" void kernel_launch(void* const* d_in, const int* in_sizes, int n_in,
                              void* d_out, int out_size) {
    (void)in_sizes; (void)n_in; (void)out_size;
    const float* x      = (const float*)d_in[0];
    const float* w_qkv  = (const float*)d_in[1];
    const float* w_proj = (const float*)d_in[2];
    const float* gamma  = (const float*)d_in[3];
    const float* beta   = (const float*)d_in[4];
    float* out = (float*)d_out;

    cudaFuncSetAttribute(k_attn, cudaFuncAttributeMaxDynamicSharedMemorySize,
                         SM_TOT * (int)sizeof(float));

    k_sgemm<<<dim3(32, 12), 256>>>(w_qkv, x, 0);          // qkv: [768][4096]
    k_prep<<<dim3(128, 3), 256>>>();                       // q,k l2norm + transpose; v transpose
    k_attn<<<dim3(512, 8), 512, SM_TOT * sizeof(float)>>>();
    k_sgemm<<<dim3(32, 4), 256>>>(w_proj, nullptr, 1);     // proj: [256][4096]
    k_gn<<<32, 256>>>(gamma, beta, out);
}